// round 15
// baseline (speedup 1.0000x reference)
#include <cuda_runtime.h>
#include <cuda_bf16.h>
#include <cstdint>

#define BATCH 1024
#define T     336
#define PRED  96
#define D     64
#define HD    64
#define G     256
#define NROWS (BATCH * T)

typedef unsigned long long ull;

// Scratch (device globals: allocation-free per harness rules)
__device__ float g_p[(size_t)BATCH * T * G];       // gate pre-acts (352 MB, bias INCLUDED)
__device__ float g_h1[(size_t)BATCH * T * HD];     // layer-0 hidden states (88 MB)
__device__ float g_h2last[BATCH * HD];

// Packed fp32x2 FMA (Blackwell — PTX-only)
#define FMA2(acc, a, b) \
    asm("fma.rn.f32x2 %0, %1, %2, %0;" : "+l"(acc) : "l"(a), "l"(b))
#define UNPACK2(lo, hi, v) \
    asm("mov.b64 {%0, %1}, %2;" : "=f"(lo), "=f"(hi) : "l"(v))

// HW tanh unit: 1 MUFU
__device__ __forceinline__ float fast_tanh(float x) {
    float y;
    asm("tanh.approx.f32 %0, %1;" : "=f"(y) : "f"(x));
    return y;
}
__device__ __forceinline__ float fast_sigmoid(float x) {
    return fmaf(fast_tanh(0.5f * x), 0.5f, 0.5f);
}

// SW128 swizzle on byte offsets (XOR bits[6:4] with bits[9:7])
#define SWZ(off) ((off) ^ (((off) >> 3) & 0x70))

// Legacy tensor-core MMA: baseline PTX (sm_80+), no 'a' feature needed.
__device__ __forceinline__ void mma_bf16(float* d,
                                         uint32_t a0, uint32_t a1,
                                         uint32_t a2, uint32_t a3,
                                         uint32_t b0, uint32_t b1) {
    asm("mma.sync.aligned.m16n8k16.row.col.f32.bf16.bf16.f32 "
        "{%0,%1,%2,%3}, {%4,%5,%6,%7}, {%8,%9}, {%0,%1,%2,%3};"
        : "+f"(d[0]), "+f"(d[1]), "+f"(d[2]), "+f"(d[3])
        : "r"(a0), "r"(a1), "r"(a2), "r"(a3), "r"(b0), "r"(b1));
}

// smem plane offsets (bytes, dynamic smem)
#define SM_BH   0                       // W hi plane: 256 rows x 128B = 32 KB
#define SM_BL   32768                   // W lo plane: 32 KB
#define SM_AH   65536                   // A hi plane: 64 rows x 128B = 8 KB
#define SM_AL   73728                   // A lo plane: 8 KB
#define SM_BIAS 81920                   // 256 floats = 1 KB
#define SM_TOT  82944

// split a float4 into hi/lo bf16 pairs (packed uint32: low half = first elem)
__device__ __forceinline__ void split4(float4 v, uint32_t& hi01, uint32_t& hi23,
                                       uint32_t& lo01, uint32_t& lo23) {
    __nv_bfloat162 h01 = __floats2bfloat162_rn(v.x, v.y);
    __nv_bfloat162 h23 = __floats2bfloat162_rn(v.z, v.w);
    __nv_bfloat162 l01 = __floats2bfloat162_rn(
        v.x - __bfloat162float(h01.x), v.y - __bfloat162float(h01.y));
    __nv_bfloat162 l23 = __floats2bfloat162_rn(
        v.z - __bfloat162float(h23.x), v.w - __bfloat162float(h23.y));
    hi01 = *(uint32_t*)&h01; hi23 = *(uint32_t*)&h23;
    lo01 = *(uint32_t*)&l01; lo23 = *(uint32_t*)&l23;
}

// ---------------------------------------------------------------------------
// HMMA input GEMM: P[r][g] = In[r]·W[g] + b1[g] + b2[g]
// Tile = 64 rows x 256 gates x K64. 512 threads = 16 warps (4 rowgrp x 4 colgrp).
// bf16 split-2: products hi*hi + hi*lo + lo*hi (lo*lo negligible), fp32 acc.
// ---------------------------------------------------------------------------
__global__ void __launch_bounds__(512, 1) input_gemm_mma(
    const float* __restrict__ In,   // [N, 64]
    const float* __restrict__ W,    // [256, 64]
    const float* __restrict__ b1,
    const float* __restrict__ b2,
    float* __restrict__ P,          // [N, 256]
    int N)
{
    extern __shared__ __align__(128) char sm[];
    float* sBias = (float*)(sm + SM_BIAS);

    const int tid  = threadIdx.x;
    const int wid  = tid >> 5;
    const int lane = tid & 31;
    const int gid  = lane >> 2;         // 0..7
    const int tig  = lane & 3;          // 0..3

    // ---- one-time W split into BH/BL planes (SW128 swizzled) + bias ----
    {
        int row  = tid >> 1;            // 0..255
        int half = tid & 1;             // elems [half*32, half*32+32)
        const float* wr = W + row * 64 + half * 32;
        uint32_t base = row * 128;
        uint32_t m    = ((uint32_t)(row & 7)) * 16;
        #pragma unroll
        for (int c = 0; c < 4; c++) {   // 4 chunks of 8 elems
            float4 v0 = *(const float4*)(wr + c * 8);
            float4 v1 = *(const float4*)(wr + c * 8 + 4);
            uint4 h, l;
            split4(v0, h.x, h.y, l.x, l.y);
            split4(v1, h.z, h.w, l.z, l.w);
            uint32_t off = base + (((uint32_t)(half * 64 + c * 16)) ^ m);
            *(uint4*)(sm + SM_BH + off) = h;
            *(uint4*)(sm + SM_BL + off) = l;
        }
        if (tid < 256) sBias[tid] = b1[tid] + b2[tid];
    }
    __syncthreads();

    const int rg = wid & 3, cg = wid >> 2;
    const int R0 = rg * 16, C0 = cg * 64;
    const uint32_t xm = ((uint32_t)gid) * 16;   // frag-load swizzle mask

    const int ntiles = N / 64;          // 5376
    const int stride = gridDim.x;
    int tile = blockIdx.x;
    if (tile >= ntiles) return;

    // A conversion identity
    const int arow = tid >> 3;          // 0..63
    const int aseg = tid & 7;           // 8 floats each
    const uint32_t am = ((uint32_t)(arow & 7)) * 16;

    float4 xr0 = *(const float4*)(In + ((size_t)tile * 64 + arow) * 64 + aseg * 8);
    float4 xr1 = *(const float4*)(In + ((size_t)tile * 64 + arow) * 64 + aseg * 8 + 4);

    for (; tile < ntiles; tile += stride) {
        // ---- split A tile into AH/AL planes ----
        {
            uint4 h, l;
            split4(xr0, h.x, h.y, l.x, l.y);
            split4(xr1, h.z, h.w, l.z, l.w);
            uint32_t off = arow * 128 + (((uint32_t)(aseg * 16)) ^ am);
            *(uint4*)(sm + SM_AH + off) = h;
            *(uint4*)(sm + SM_AL + off) = l;
        }
        __syncthreads();

        // prefetch next tile
        const int nxt = tile + stride;
        if (nxt < ntiles) {
            xr0 = *(const float4*)(In + ((size_t)nxt * 64 + arow) * 64 + aseg * 8);
            xr1 = *(const float4*)(In + ((size_t)nxt * 64 + arow) * 64 + aseg * 8 + 4);
        }

        // ---- MMA mainloop ----
        float acc[8][4];
        #pragma unroll
        for (int n = 0; n < 8; n++)
            { acc[n][0] = 0.f; acc[n][1] = 0.f; acc[n][2] = 0.f; acc[n][3] = 0.f; }

        #pragma unroll
        for (int kc = 0; kc < 4; kc++) {
            const uint32_t kb0 = (uint32_t)(kc * 32 + tig * 4);
            const uint32_t kb1 = kb0 + 16;
            const uint32_t ra  = (uint32_t)((R0 + gid) * 128);
            uint32_t ah0 = *(const uint32_t*)(sm + SM_AH + ra        + (kb0 ^ xm));
            uint32_t ah1 = *(const uint32_t*)(sm + SM_AH + ra + 1024 + (kb0 ^ xm));
            uint32_t ah2 = *(const uint32_t*)(sm + SM_AH + ra        + (kb1 ^ xm));
            uint32_t ah3 = *(const uint32_t*)(sm + SM_AH + ra + 1024 + (kb1 ^ xm));
            uint32_t al0 = *(const uint32_t*)(sm + SM_AL + ra        + (kb0 ^ xm));
            uint32_t al1 = *(const uint32_t*)(sm + SM_AL + ra + 1024 + (kb0 ^ xm));
            uint32_t al2 = *(const uint32_t*)(sm + SM_AL + ra        + (kb1 ^ xm));
            uint32_t al3 = *(const uint32_t*)(sm + SM_AL + ra + 1024 + (kb1 ^ xm));
            #pragma unroll
            for (int n8 = 0; n8 < 8; n8++) {
                const uint32_t rb = (uint32_t)((C0 + n8 * 8 + gid) * 128);
                uint32_t bh0 = *(const uint32_t*)(sm + SM_BH + rb + (kb0 ^ xm));
                uint32_t bh1 = *(const uint32_t*)(sm + SM_BH + rb + (kb1 ^ xm));
                uint32_t bl0 = *(const uint32_t*)(sm + SM_BL + rb + (kb0 ^ xm));
                uint32_t bl1 = *(const uint32_t*)(sm + SM_BL + rb + (kb1 ^ xm));
                mma_bf16(acc[n8], ah0, ah1, ah2, ah3, bh0, bh1);
                mma_bf16(acc[n8], ah0, ah1, ah2, ah3, bl0, bl1);
                mma_bf16(acc[n8], al0, al1, al2, al3, bh0, bh1);
            }
        }

        // ---- epilogue: add bias, stream to P ----
        {
            const size_t r0 = (size_t)tile * 64 + R0 + gid;
            #pragma unroll
            for (int n8 = 0; n8 < 8; n8++) {
                const int col = C0 + n8 * 8 + tig * 2;
                float2 bb = *(const float2*)&sBias[col];
                float2 v0 = make_float2(acc[n8][0] + bb.x, acc[n8][1] + bb.y);
                float2 v1 = make_float2(acc[n8][2] + bb.x, acc[n8][3] + bb.y);
                __stcs((float2*)(P + r0 * G + col), v0);
                __stcs((float2*)(P + (r0 + 8) * G + col), v1);
            }
        }
        __syncthreads();   // A planes safe to overwrite
    }
}

// ---------------------------------------------------------------------------
// Recurrent scan (R8/R10 — known good 425us): BT=4, 256 thr, 2 CTAs/SM.
// P includes bias.
// ---------------------------------------------------------------------------
template <bool WRITE_ALL>
__global__ void __launch_bounds__(256, 2) lstm_recur(
    const float* __restrict__ P,     // [BATCH, T, 256] (biases included)
    const float* __restrict__ Whh,   // [256, 64]
    float* __restrict__ hout)        // WRITE_ALL ? [BATCH,T,64] : [BATCH,64]
{
    __shared__ __align__(16) float sH[4 * 64];
    __shared__ __align__(16) float sGate[4 * G];

    const int tid = threadIdx.x;
    const int b0  = blockIdx.x * 4;
    const int g   = tid;
    const int gt  = g >> 6;              // warp-uniform

    ull w[32];
    {
        const ull* wp = (const ull*)(Whh + g * 64);
        #pragma unroll
        for (int i = 0; i < 32; i++) w[i] = wp[i];
    }

    const int eb = tid >> 6;             // 0..3
    const int ej = tid & 63;
    float c = 0.0f;

    sH[tid] = 0.0f;

    const float* pbase = P + ((size_t)b0 * T) * G + g;
    float pc[4];
    #pragma unroll
    for (int b = 0; b < 4; b++) pc[b] = pbase[(size_t)b * T * G];
    __syncthreads();

    for (int t = 0; t < T; t++) {
        float pn[4];
        if (t + 1 < T) {
            #pragma unroll
            for (int b = 0; b < 4; b++)
                pn[b] = __ldcs(&pbase[(size_t)b * T * G + (size_t)(t + 1) * G]);
        }

        ull acc[4];
        #pragma unroll
        for (int b = 0; b < 4; b++) acc[b] = 0ull;

        #pragma unroll
        for (int kg = 0; kg < 16; kg++) {
            ull w01 = w[2 * kg], w23 = w[2 * kg + 1];
            #pragma unroll
            for (int b = 0; b < 4; b++) {
                ulonglong2 hv = *(const ulonglong2*)&sH[b * 64 + kg * 4];
                FMA2(acc[b], w01, hv.x);
                FMA2(acc[b], w23, hv.y);
            }
        }

        #pragma unroll
        for (int b = 0; b < 4; b++) {
            float lo, hi;
            UNPACK2(lo, hi, acc[b]);
            float v = lo + hi + pc[b];
            sGate[b * G + g] = (gt == 2) ? fast_tanh(v) : fast_sigmoid(v);
        }
        __syncthreads();

        {
            float iv = sGate[eb * G + ej];
            float fv = sGate[eb * G + 64 + ej];
            float gv = sGate[eb * G + 128 + ej];
            float ov = sGate[eb * G + 192 + ej];
            c = fmaf(fv, c, iv * gv);
            float h = ov * fast_tanh(c);
            sH[tid] = h;
            if (WRITE_ALL) {
                __stcs(&hout[(size_t)(b0 + eb) * T * HD + (size_t)t * HD + ej], h);
            } else if (t == T - 1) {
                hout[(b0 + eb) * HD + ej] = h;
            }
        }
        __syncthreads();

        #pragma unroll
        for (int b = 0; b < 4; b++) pc[b] = pn[b];
    }
}

// ---------------------------------------------------------------------------
// Decoder v2 (R8/R10, unchanged): BT=4, 256 thr, 2 CTAs/SM.
// ---------------------------------------------------------------------------
__global__ void __launch_bounds__(256, 2) lstm_decoder(
    const float* __restrict__ Wih0, const float* __restrict__ bih0, const float* __restrict__ bhh0,
    const float* __restrict__ Wih1, const float* __restrict__ bih1, const float* __restrict__ bhh1,
    const float* __restrict__ Wfc,  const float* __restrict__ bfc,
    const float* __restrict__ h2last,
    float* __restrict__ out)   // [BATCH, PRED, 64]
{
    extern __shared__ __align__(16) char dyn[];
    ull*   sW1p  = (ull*)dyn;                      // [32][256] ull (64 KB)
    ull*   sWfcp = sW1p + 32 * 256;                // [32][64]  ull (16 KB)
    float* sB1   = (float*)(sWfcp + 32 * 64);      // [256]
    float* sBfc  = sB1 + 256;                      // [64]
    float* sIn   = sBfc + 64;                      // [4][64]
    float* sHm   = sIn + 4 * 64;                   // [4][64]
    float* sGate = sHm + 4 * 64;                   // [4][256]

    const int tid = threadIdx.x;
    const int b0  = blockIdx.x * 4;
    const int g   = tid;
    const int gt  = g >> 6;
    const int eb  = tid >> 6;            // 0..3
    const int ej  = tid & 63;

    ull wa[32];
    {
        const ull* w0 = (const ull*)(Wih0 + g * 64);
        #pragma unroll
        for (int i = 0; i < 32; i++) wa[i] = w0[i];
    }
    const float bias0 = bih0[g] + bhh0[g];
    const float ta = (gt == 2) ? 1.0f : 0.5f;
    const float s1 = (gt == 2) ? 1.0f : 0.5f;
    const float s2 = (gt == 2) ? 0.0f : 0.5f;

    {
        const ull* w1 = (const ull*)(Wih1 + tid * 64);
        #pragma unroll
        for (int i = 0; i < 32; i++) sW1p[i * 256 + tid] = w1[i];
        sB1[tid] = bih1[tid] + bhh1[tid];
        if (tid < 64) {
            const ull* wf = (const ull*)(Wfc + tid * 64);
            #pragma unroll
            for (int i = 0; i < 32; i++) sWfcp[i * 64 + tid] = wf[i];
            sBfc[tid] = bfc[tid];
        }
    }
    sIn[tid] = h2last[b0 * 64 + tid];
    __syncthreads();

    for (int s = 0; s < PRED; s++) {
        // ---- cell0 (weights in regs), src = sIn ----
        {
            ull acc[4];
            #pragma unroll
            for (int b = 0; b < 4; b++) acc[b] = 0ull;
            #pragma unroll
            for (int kg = 0; kg < 16; kg++) {
                ull w01 = wa[2 * kg], w23 = wa[2 * kg + 1];
                #pragma unroll
                for (int b = 0; b < 4; b++) {
                    ulonglong2 xv = *(const ulonglong2*)&sIn[b * 64 + kg * 4];
                    FMA2(acc[b], w01, xv.x);
                    FMA2(acc[b], w23, xv.y);
                }
            }
            #pragma unroll
            for (int b = 0; b < 4; b++) {
                float lo, hi;
                UNPACK2(lo, hi, acc[b]);
                float v = lo + hi + bias0;
                sGate[b * G + g] = fmaf(fast_tanh(v * ta), s1, s2);
            }
            __syncthreads();
            float iv = sGate[eb * G + ej];
            float gv = sGate[eb * G + 128 + ej];
            float ov = sGate[eb * G + 192 + ej];
            sHm[tid] = ov * fast_tanh(iv * gv);
            __syncthreads();
        }
        // ---- cell1 (weights from packed smem), src = sHm ----
        {
            ull acc[4];
            #pragma unroll
            for (int b = 0; b < 4; b++) acc[b] = 0ull;
            #pragma unroll
            for (int kg = 0; kg < 16; kg++) {
                ull w01 = sW1p[(2 * kg) * 256 + g];
                ull w23 = sW1p[(2 * kg + 1) * 256 + g];
                #pragma unroll
                for (int b = 0; b < 4; b++) {
                    ulonglong2 xv = *(const ulonglong2*)&sHm[b * 64 + kg * 4];
                    FMA2(acc[b], w01, xv.x);
                    FMA2(acc[b], w23, xv.y);
                }
            }
            float bias1 = sB1[g];
            #pragma unroll
            for (int b = 0; b < 4; b++) {
                float lo, hi;
                UNPACK2(lo, hi, acc[b]);
                float v = lo + hi + bias1;
                sGate[b * G + g] = fmaf(fast_tanh(v * ta), s1, s2);
            }
            __syncthreads();
            float iv = sGate[eb * G + ej];
            float gv = sGate[eb * G + 128 + ej];
            float ov = sGate[eb * G + 192 + ej];
            sHm[tid] = ov * fast_tanh(iv * gv);
            __syncthreads();
        }
        // ---- FC: one output per thread (eb, ej) ----
        {
            ull acc = 0ull;
            #pragma unroll
            for (int i = 0; i < 16; i++) {
                ull w01 = sWfcp[(2 * i) * 64 + ej];
                ull w23 = sWfcp[(2 * i + 1) * 64 + ej];
                ulonglong2 xv = *(const ulonglong2*)&sHm[eb * 64 + i * 4];
                FMA2(acc, w01, xv.x);
                FMA2(acc, w23, xv.y);
            }
            float lo, hi;
            UNPACK2(lo, hi, acc);
            float pred = lo + hi + sBfc[ej];
            out[(size_t)(b0 + eb) * PRED * HD + (size_t)s * HD + ej] = pred;
            sIn[tid] = pred;
            __syncthreads();
        }
    }
}

// ---------------------------------------------------------------------------
extern "C" void kernel_launch(void* const* d_in, const int* in_sizes, int n_in,
                              void* d_out, int out_size)
{
    const float* x    = (const float*)d_in[0];
    const float* Wih0 = (const float*)d_in[1];
    const float* Whh0 = (const float*)d_in[2];
    const float* bih0 = (const float*)d_in[3];
    const float* bhh0 = (const float*)d_in[4];
    const float* Wih1 = (const float*)d_in[5];
    const float* Whh1 = (const float*)d_in[6];
    const float* bih1 = (const float*)d_in[7];
    const float* bhh1 = (const float*)d_in[8];
    const float* Wfc  = (const float*)d_in[9];
    const float* bfc  = (const float*)d_in[10];
    float* out = (float*)d_out;

    float *pbuf = nullptr, *h1 = nullptr, *h2l = nullptr;
    cudaGetSymbolAddress((void**)&pbuf, g_p);
    cudaGetSymbolAddress((void**)&h1,   g_h1);
    cudaGetSymbolAddress((void**)&h2l,  g_h2last);

    const size_t smDec = (32 * 256 + 32 * 64) * sizeof(ull)
                       + (256 + 64 + 4 * 64 * 2 + 4 * G) * sizeof(float);
    cudaFuncSetAttribute(lstm_decoder, cudaFuncAttributeMaxDynamicSharedMemorySize, (int)smDec);
    cudaFuncSetAttribute(input_gemm_mma, cudaFuncAttributeMaxDynamicSharedMemorySize, SM_TOT);

    input_gemm_mma<<<148, 512, SM_TOT>>>(x, Wih0, bih0, bhh0, pbuf, NROWS);
    lstm_recur<true ><<<256, 256>>>(pbuf, Whh0, h1);

    input_gemm_mma<<<148, 512, SM_TOT>>>(h1, Wih1, bih1, bhh1, pbuf, NROWS);
    lstm_recur<false><<<256, 256>>>(pbuf, Whh1, h2l);

    lstm_decoder<<<256, 256, smDec>>>(Wih0, bih0, bhh0, Wih1, bih1, bhh1,
                                      Wfc, bfc, h2l, out);
}

// round 16
// speedup vs baseline: 1.6224x; 1.6224x over previous
#include <cuda_runtime.h>
#include <cuda_bf16.h>
#include <cstdint>

#define BATCH 1024
#define T     336
#define PRED  96
#define D     64
#define HD    64
#define G     256
#define NROWS (BATCH * T)

typedef unsigned long long ull;

// Scratch (device globals: allocation-free per harness rules)
__device__ float g_p[(size_t)BATCH * T * G];       // gate pre-acts (352 MB, bias INCLUDED)
__device__ float g_h1[(size_t)BATCH * T * HD];     // layer-0 hidden states (88 MB)
__device__ float g_h2last[BATCH * HD];

// Packed fp32x2 FMA (Blackwell — PTX-only)
#define FMA2(acc, a, b) \
    asm("fma.rn.f32x2 %0, %1, %2, %0;" : "+l"(acc) : "l"(a), "l"(b))
#define UNPACK2(lo, hi, v) \
    asm("mov.b64 {%0, %1}, %2;" : "=f"(lo), "=f"(hi) : "l"(v))

// HW tanh unit: 1 MUFU
__device__ __forceinline__ float fast_tanh(float x) {
    float y;
    asm("tanh.approx.f32 %0, %1;" : "=f"(y) : "f"(x));
    return y;
}
__device__ __forceinline__ float fast_sigmoid(float x) {
    return fmaf(fast_tanh(0.5f * x), 0.5f, 0.5f);
}

// SW128 swizzle on byte offsets (XOR bits[6:4] with bits[9:7])
#define SWZ(off) ((off) ^ (((off) >> 3) & 0x70))

// Legacy tensor-core MMA: baseline PTX (sm_80+), no 'a' feature needed.
__device__ __forceinline__ void mma_bf16(float* d,
                                         uint32_t a0, uint32_t a1,
                                         uint32_t a2, uint32_t a3,
                                         uint32_t b0, uint32_t b1) {
    asm("mma.sync.aligned.m16n8k16.row.col.f32.bf16.bf16.f32 "
        "{%0,%1,%2,%3}, {%4,%5,%6,%7}, {%8,%9}, {%0,%1,%2,%3};"
        : "+f"(d[0]), "+f"(d[1]), "+f"(d[2]), "+f"(d[3])
        : "r"(a0), "r"(a1), "r"(a2), "r"(a3), "r"(b0), "r"(b1));
}

// smem plane offsets (bytes, dynamic smem)
#define SM_BH   0                       // W hi plane: 256 rows x 128B = 32 KB
#define SM_BL   32768                   // W lo plane: 32 KB
#define SM_AH   65536                   // A hi plane: 64 rows x 128B = 8 KB
#define SM_AL   73728                   // A lo plane: 8 KB
#define SM_BIAS 81920                   // 256 floats = 1 KB
#define SM_TOT  82944

// split a float4 into hi/lo bf16 pairs (packed uint32: low half = first elem)
__device__ __forceinline__ void split4(float4 v, uint32_t& hi01, uint32_t& hi23,
                                       uint32_t& lo01, uint32_t& lo23) {
    __nv_bfloat162 h01 = __floats2bfloat162_rn(v.x, v.y);
    __nv_bfloat162 h23 = __floats2bfloat162_rn(v.z, v.w);
    __nv_bfloat162 l01 = __floats2bfloat162_rn(
        v.x - __bfloat162float(h01.x), v.y - __bfloat162float(h01.y));
    __nv_bfloat162 l23 = __floats2bfloat162_rn(
        v.z - __bfloat162float(h23.x), v.w - __bfloat162float(h23.y));
    hi01 = *(uint32_t*)&h01; hi23 = *(uint32_t*)&h23;
    lo01 = *(uint32_t*)&l01; lo23 = *(uint32_t*)&l23;
}

// ---------------------------------------------------------------------------
// HMMA input GEMM: P[r][g] = In[r]·W[g] + b1[g] + b2[g]
// Tile = 64 rows x 256 gates x K64. 512 threads = 16 warps (4 rowgrp x 4 colgrp).
// bf16 split-2: products hi*hi + hi*lo + lo*hi (lo*lo negligible), fp32 acc.
// ---------------------------------------------------------------------------
__global__ void __launch_bounds__(512, 1) input_gemm_mma(
    const float* __restrict__ In,   // [N, 64]
    const float* __restrict__ W,    // [256, 64]
    const float* __restrict__ b1,
    const float* __restrict__ b2,
    float* __restrict__ P,          // [N, 256]
    int N)
{
    extern __shared__ __align__(128) char sm[];
    float* sBias = (float*)(sm + SM_BIAS);

    const int tid  = threadIdx.x;
    const int wid  = tid >> 5;
    const int lane = tid & 31;
    const int gid  = lane >> 2;         // 0..7
    const int tig  = lane & 3;          // 0..3

    // ---- one-time W split into BH/BL planes (SW128 swizzled) + bias ----
    {
        int row  = tid >> 1;            // 0..255
        int half = tid & 1;             // elems [half*32, half*32+32)
        const float* wr = W + row * 64 + half * 32;
        uint32_t base = row * 128;
        uint32_t m    = ((uint32_t)(row & 7)) * 16;
        #pragma unroll
        for (int c = 0; c < 4; c++) {   // 4 chunks of 8 elems
            float4 v0 = *(const float4*)(wr + c * 8);
            float4 v1 = *(const float4*)(wr + c * 8 + 4);
            uint4 h, l;
            split4(v0, h.x, h.y, l.x, l.y);
            split4(v1, h.z, h.w, l.z, l.w);
            uint32_t off = base + (((uint32_t)(half * 64 + c * 16)) ^ m);
            *(uint4*)(sm + SM_BH + off) = h;
            *(uint4*)(sm + SM_BL + off) = l;
        }
        if (tid < 256) sBias[tid] = b1[tid] + b2[tid];
    }
    __syncthreads();

    const int rg = wid & 3, cg = wid >> 2;
    const int R0 = rg * 16, C0 = cg * 64;
    const uint32_t xm = ((uint32_t)gid) * 16;   // frag-load swizzle mask

    const int ntiles = N / 64;          // 5376
    const int stride = gridDim.x;
    int tile = blockIdx.x;
    if (tile >= ntiles) return;

    // A conversion identity
    const int arow = tid >> 3;          // 0..63
    const int aseg = tid & 7;           // 8 floats each
    const uint32_t am = ((uint32_t)(arow & 7)) * 16;

    float4 xr0 = *(const float4*)(In + ((size_t)tile * 64 + arow) * 64 + aseg * 8);
    float4 xr1 = *(const float4*)(In + ((size_t)tile * 64 + arow) * 64 + aseg * 8 + 4);

    for (; tile < ntiles; tile += stride) {
        // ---- split A tile into AH/AL planes ----
        {
            uint4 h, l;
            split4(xr0, h.x, h.y, l.x, l.y);
            split4(xr1, h.z, h.w, l.z, l.w);
            uint32_t off = arow * 128 + (((uint32_t)(aseg * 16)) ^ am);
            *(uint4*)(sm + SM_AH + off) = h;
            *(uint4*)(sm + SM_AL + off) = l;
        }
        __syncthreads();

        // prefetch next tile
        const int nxt = tile + stride;
        if (nxt < ntiles) {
            xr0 = *(const float4*)(In + ((size_t)nxt * 64 + arow) * 64 + aseg * 8);
            xr1 = *(const float4*)(In + ((size_t)nxt * 64 + arow) * 64 + aseg * 8 + 4);
        }

        // ---- MMA mainloop ----
        float acc[8][4];
        #pragma unroll
        for (int n = 0; n < 8; n++)
            { acc[n][0] = 0.f; acc[n][1] = 0.f; acc[n][2] = 0.f; acc[n][3] = 0.f; }

        #pragma unroll
        for (int kc = 0; kc < 4; kc++) {
            const uint32_t kb0 = (uint32_t)(kc * 32 + tig * 4);
            const uint32_t kb1 = kb0 + 16;
            const uint32_t ra  = (uint32_t)((R0 + gid) * 128);
            uint32_t ah0 = *(const uint32_t*)(sm + SM_AH + ra        + (kb0 ^ xm));
            uint32_t ah1 = *(const uint32_t*)(sm + SM_AH + ra + 1024 + (kb0 ^ xm));
            uint32_t ah2 = *(const uint32_t*)(sm + SM_AH + ra        + (kb1 ^ xm));
            uint32_t ah3 = *(const uint32_t*)(sm + SM_AH + ra + 1024 + (kb1 ^ xm));
            uint32_t al0 = *(const uint32_t*)(sm + SM_AL + ra        + (kb0 ^ xm));
            uint32_t al1 = *(const uint32_t*)(sm + SM_AL + ra + 1024 + (kb0 ^ xm));
            uint32_t al2 = *(const uint32_t*)(sm + SM_AL + ra        + (kb1 ^ xm));
            uint32_t al3 = *(const uint32_t*)(sm + SM_AL + ra + 1024 + (kb1 ^ xm));
            #pragma unroll
            for (int n8 = 0; n8 < 8; n8++) {
                const uint32_t rb = (uint32_t)((C0 + n8 * 8 + gid) * 128);
                uint32_t bh0 = *(const uint32_t*)(sm + SM_BH + rb + (kb0 ^ xm));
                uint32_t bh1 = *(const uint32_t*)(sm + SM_BH + rb + (kb1 ^ xm));
                uint32_t bl0 = *(const uint32_t*)(sm + SM_BL + rb + (kb0 ^ xm));
                uint32_t bl1 = *(const uint32_t*)(sm + SM_BL + rb + (kb1 ^ xm));
                mma_bf16(acc[n8], ah0, ah1, ah2, ah3, bh0, bh1);
                mma_bf16(acc[n8], ah0, ah1, ah2, ah3, bl0, bl1);
                mma_bf16(acc[n8], al0, al1, al2, al3, bh0, bh1);
            }
        }

        // ---- epilogue: add bias, stream to P ----
        {
            const size_t r0 = (size_t)tile * 64 + R0 + gid;
            #pragma unroll
            for (int n8 = 0; n8 < 8; n8++) {
                const int col = C0 + n8 * 8 + tig * 2;
                float2 bb = *(const float2*)&sBias[col];
                float2 v0 = make_float2(acc[n8][0] + bb.x, acc[n8][1] + bb.y);
                float2 v1 = make_float2(acc[n8][2] + bb.x, acc[n8][3] + bb.y);
                __stcs((float2*)(P + r0 * G + col), v0);
                __stcs((float2*)(P + (r0 + 8) * G + col), v1);
            }
        }
        __syncthreads();   // A planes safe to overwrite
    }
}

// ---------------------------------------------------------------------------
// Recurrent scan (R8/R10 — known good 425us): BT=4, 256 thr, 2 CTAs/SM.
// P includes bias.
// ---------------------------------------------------------------------------
template <bool WRITE_ALL>
__global__ void __launch_bounds__(256, 2) lstm_recur(
    const float* __restrict__ P,     // [BATCH, T, 256] (biases included)
    const float* __restrict__ Whh,   // [256, 64]
    float* __restrict__ hout)        // WRITE_ALL ? [BATCH,T,64] : [BATCH,64]
{
    __shared__ __align__(16) float sH[4 * 64];
    __shared__ __align__(16) float sGate[4 * G];

    const int tid = threadIdx.x;
    const int b0  = blockIdx.x * 4;
    const int g   = tid;
    const int gt  = g >> 6;              // warp-uniform

    ull w[32];
    {
        const ull* wp = (const ull*)(Whh + g * 64);
        #pragma unroll
        for (int i = 0; i < 32; i++) w[i] = wp[i];
    }

    const int eb = tid >> 6;             // 0..3
    const int ej = tid & 63;
    float c = 0.0f;

    sH[tid] = 0.0f;

    const float* pbase = P + ((size_t)b0 * T) * G + g;
    float pc[4];
    #pragma unroll
    for (int b = 0; b < 4; b++) pc[b] = pbase[(size_t)b * T * G];
    __syncthreads();

    for (int t = 0; t < T; t++) {
        float pn[4];
        if (t + 1 < T) {
            #pragma unroll
            for (int b = 0; b < 4; b++)
                pn[b] = __ldcs(&pbase[(size_t)b * T * G + (size_t)(t + 1) * G]);
        }

        ull acc[4];
        #pragma unroll
        for (int b = 0; b < 4; b++) acc[b] = 0ull;

        #pragma unroll
        for (int kg = 0; kg < 16; kg++) {
            ull w01 = w[2 * kg], w23 = w[2 * kg + 1];
            #pragma unroll
            for (int b = 0; b < 4; b++) {
                ulonglong2 hv = *(const ulonglong2*)&sH[b * 64 + kg * 4];
                FMA2(acc[b], w01, hv.x);
                FMA2(acc[b], w23, hv.y);
            }
        }

        #pragma unroll
        for (int b = 0; b < 4; b++) {
            float lo, hi;
            UNPACK2(lo, hi, acc[b]);
            float v = lo + hi + pc[b];
            sGate[b * G + g] = (gt == 2) ? fast_tanh(v) : fast_sigmoid(v);
        }
        __syncthreads();

        {
            float iv = sGate[eb * G + ej];
            float fv = sGate[eb * G + 64 + ej];
            float gv = sGate[eb * G + 128 + ej];
            float ov = sGate[eb * G + 192 + ej];
            c = fmaf(fv, c, iv * gv);
            float h = ov * fast_tanh(c);
            sH[tid] = h;
            if (WRITE_ALL) {
                __stcs(&hout[(size_t)(b0 + eb) * T * HD + (size_t)t * HD + ej], h);
            } else if (t == T - 1) {
                hout[(b0 + eb) * HD + ej] = h;
            }
        }
        __syncthreads();

        #pragma unroll
        for (int b = 0; b < 4; b++) pc[b] = pn[b];
    }
}

// ---------------------------------------------------------------------------
// Decoder v2 (R8/R10, unchanged): BT=4, 256 thr, 2 CTAs/SM.
// ---------------------------------------------------------------------------
__global__ void __launch_bounds__(256, 2) lstm_decoder(
    const float* __restrict__ Wih0, const float* __restrict__ bih0, const float* __restrict__ bhh0,
    const float* __restrict__ Wih1, const float* __restrict__ bih1, const float* __restrict__ bhh1,
    const float* __restrict__ Wfc,  const float* __restrict__ bfc,
    const float* __restrict__ h2last,
    float* __restrict__ out)   // [BATCH, PRED, 64]
{
    extern __shared__ __align__(16) char dyn[];
    ull*   sW1p  = (ull*)dyn;                      // [32][256] ull (64 KB)
    ull*   sWfcp = sW1p + 32 * 256;                // [32][64]  ull (16 KB)
    float* sB1   = (float*)(sWfcp + 32 * 64);      // [256]
    float* sBfc  = sB1 + 256;                      // [64]
    float* sIn   = sBfc + 64;                      // [4][64]
    float* sHm   = sIn + 4 * 64;                   // [4][64]
    float* sGate = sHm + 4 * 64;                   // [4][256]

    const int tid = threadIdx.x;
    const int b0  = blockIdx.x * 4;
    const int g   = tid;
    const int gt  = g >> 6;
    const int eb  = tid >> 6;            // 0..3
    const int ej  = tid & 63;

    ull wa[32];
    {
        const ull* w0 = (const ull*)(Wih0 + g * 64);
        #pragma unroll
        for (int i = 0; i < 32; i++) wa[i] = w0[i];
    }
    const float bias0 = bih0[g] + bhh0[g];
    const float ta = (gt == 2) ? 1.0f : 0.5f;
    const float s1 = (gt == 2) ? 1.0f : 0.5f;
    const float s2 = (gt == 2) ? 0.0f : 0.5f;

    {
        const ull* w1 = (const ull*)(Wih1 + tid * 64);
        #pragma unroll
        for (int i = 0; i < 32; i++) sW1p[i * 256 + tid] = w1[i];
        sB1[tid] = bih1[tid] + bhh1[tid];
        if (tid < 64) {
            const ull* wf = (const ull*)(Wfc + tid * 64);
            #pragma unroll
            for (int i = 0; i < 32; i++) sWfcp[i * 64 + tid] = wf[i];
            sBfc[tid] = bfc[tid];
        }
    }
    sIn[tid] = h2last[b0 * 64 + tid];
    __syncthreads();

    for (int s = 0; s < PRED; s++) {
        // ---- cell0 (weights in regs), src = sIn ----
        {
            ull acc[4];
            #pragma unroll
            for (int b = 0; b < 4; b++) acc[b] = 0ull;
            #pragma unroll
            for (int kg = 0; kg < 16; kg++) {
                ull w01 = wa[2 * kg], w23 = wa[2 * kg + 1];
                #pragma unroll
                for (int b = 0; b < 4; b++) {
                    ulonglong2 xv = *(const ulonglong2*)&sIn[b * 64 + kg * 4];
                    FMA2(acc[b], w01, xv.x);
                    FMA2(acc[b], w23, xv.y);
                }
            }
            #pragma unroll
            for (int b = 0; b < 4; b++) {
                float lo, hi;
                UNPACK2(lo, hi, acc[b]);
                float v = lo + hi + bias0;
                sGate[b * G + g] = fmaf(fast_tanh(v * ta), s1, s2);
            }
            __syncthreads();
            float iv = sGate[eb * G + ej];
            float gv = sGate[eb * G + 128 + ej];
            float ov = sGate[eb * G + 192 + ej];
            sHm[tid] = ov * fast_tanh(iv * gv);
            __syncthreads();
        }
        // ---- cell1 (weights from packed smem), src = sHm ----
        {
            ull acc[4];
            #pragma unroll
            for (int b = 0; b < 4; b++) acc[b] = 0ull;
            #pragma unroll
            for (int kg = 0; kg < 16; kg++) {
                ull w01 = sW1p[(2 * kg) * 256 + g];
                ull w23 = sW1p[(2 * kg + 1) * 256 + g];
                #pragma unroll
                for (int b = 0; b < 4; b++) {
                    ulonglong2 xv = *(const ulonglong2*)&sHm[b * 64 + kg * 4];
                    FMA2(acc[b], w01, xv.x);
                    FMA2(acc[b], w23, xv.y);
                }
            }
            float bias1 = sB1[g];
            #pragma unroll
            for (int b = 0; b < 4; b++) {
                float lo, hi;
                UNPACK2(lo, hi, acc[b]);
                float v = lo + hi + bias1;
                sGate[b * G + g] = fmaf(fast_tanh(v * ta), s1, s2);
            }
            __syncthreads();
            float iv = sGate[eb * G + ej];
            float gv = sGate[eb * G + 128 + ej];
            float ov = sGate[eb * G + 192 + ej];
            sHm[tid] = ov * fast_tanh(iv * gv);
            __syncthreads();
        }
        // ---- FC: one output per thread (eb, ej) ----
        {
            ull acc = 0ull;
            #pragma unroll
            for (int i = 0; i < 16; i++) {
                ull w01 = sWfcp[(2 * i) * 64 + ej];
                ull w23 = sWfcp[(2 * i + 1) * 64 + ej];
                ulonglong2 xv = *(const ulonglong2*)&sHm[eb * 64 + i * 4];
                FMA2(acc, w01, xv.x);
                FMA2(acc, w23, xv.y);
            }
            float lo, hi;
            UNPACK2(lo, hi, acc);
            float pred = lo + hi + sBfc[ej];
            out[(size_t)(b0 + eb) * PRED * HD + (size_t)s * HD + ej] = pred;
            sIn[tid] = pred;
            __syncthreads();
        }
    }
}

// ---------------------------------------------------------------------------
extern "C" void kernel_launch(void* const* d_in, const int* in_sizes, int n_in,
                              void* d_out, int out_size)
{
    const float* x    = (const float*)d_in[0];
    const float* Wih0 = (const float*)d_in[1];
    const float* Whh0 = (const float*)d_in[2];
    const float* bih0 = (const float*)d_in[3];
    const float* bhh0 = (const float*)d_in[4];
    const float* Wih1 = (const float*)d_in[5];
    const float* Whh1 = (const float*)d_in[6];
    const float* bih1 = (const float*)d_in[7];
    const float* bhh1 = (const float*)d_in[8];
    const float* Wfc  = (const float*)d_in[9];
    const float* bfc  = (const float*)d_in[10];
    float* out = (float*)d_out;

    float *pbuf = nullptr, *h1 = nullptr, *h2l = nullptr;
    cudaGetSymbolAddress((void**)&pbuf, g_p);
    cudaGetSymbolAddress((void**)&h1,   g_h1);
    cudaGetSymbolAddress((void**)&h2l,  g_h2last);

    const size_t smDec = (32 * 256 + 32 * 64) * sizeof(ull)
                       + (256 + 64 + 4 * 64 * 2 + 4 * G) * sizeof(float);
    cudaFuncSetAttribute(lstm_decoder, cudaFuncAttributeMaxDynamicSharedMemorySize, (int)smDec);
    cudaFuncSetAttribute(input_gemm_mma, cudaFuncAttributeMaxDynamicSharedMemorySize, SM_TOT);

    input_gemm_mma<<<148, 512, SM_TOT>>>(x, Wih0, bih0, bhh0, pbuf, NROWS);
    lstm_recur<true ><<<256, 256>>>(pbuf, Whh0, h1);

    input_gemm_mma<<<148, 512, SM_TOT>>>(h1, Wih1, bih1, bhh1, pbuf, NROWS);
    lstm_recur<false><<<256, 256>>>(pbuf, Whh1, h2l);

    lstm_decoder<<<256, 256, smDec>>>(Wih0, bih0, bhh0, Wih1, bih1, bhh1,
                                      Wfc, bfc, h2l, out);
}

// round 17
// speedup vs baseline: 1.6244x; 1.0012x over previous
#include <cuda_runtime.h>
#include <cuda_bf16.h>
#include <cstdint>

#define BATCH 1024
#define T     336
#define PRED  96
#define D     64
#define HD    64
#define G     256
#define NROWS (BATCH * T)

typedef unsigned long long ull;

// Scratch (device globals: allocation-free per harness rules)
__device__ float g_p[(size_t)BATCH * T * G];       // gate pre-acts (352 MB, bias INCLUDED)
__device__ float g_h1[(size_t)BATCH * T * HD];     // layer-0 hidden states (88 MB)
__device__ float g_h2last[BATCH * HD];

// Packed fp32x2 FMA (Blackwell — PTX-only)
#define FMA2(acc, a, b) \
    asm("fma.rn.f32x2 %0, %1, %2, %0;" : "+l"(acc) : "l"(a), "l"(b))
#define UNPACK2(lo, hi, v) \
    asm("mov.b64 {%0, %1}, %2;" : "=f"(lo), "=f"(hi) : "l"(v))

// HW tanh unit: 1 MUFU
__device__ __forceinline__ float fast_tanh(float x) {
    float y;
    asm("tanh.approx.f32 %0, %1;" : "=f"(y) : "f"(x));
    return y;
}
__device__ __forceinline__ float fast_sigmoid(float x) {
    return fmaf(fast_tanh(0.5f * x), 0.5f, 0.5f);
}

// SW128 swizzle on byte offsets (XOR bits[6:4] with bits[9:7])
#define SWZ(off) ((off) ^ (((off) >> 3) & 0x70))

// Legacy tensor-core MMA: baseline PTX (sm_80+), no 'a' feature needed.
__device__ __forceinline__ void mma_bf16(float* d,
                                         uint32_t a0, uint32_t a1,
                                         uint32_t a2, uint32_t a3,
                                         uint32_t b0, uint32_t b1) {
    asm("mma.sync.aligned.m16n8k16.row.col.f32.bf16.bf16.f32 "
        "{%0,%1,%2,%3}, {%4,%5,%6,%7}, {%8,%9}, {%0,%1,%2,%3};"
        : "+f"(d[0]), "+f"(d[1]), "+f"(d[2]), "+f"(d[3])
        : "r"(a0), "r"(a1), "r"(a2), "r"(a3), "r"(b0), "r"(b1));
}

// smem plane offsets (bytes, dynamic smem)
#define SM_BH   0                       // W hi plane: 256 rows x 128B = 32 KB
#define SM_BL   32768                   // W lo plane: 32 KB
#define SM_AH   65536                   // A hi plane: 64 rows x 128B = 8 KB
#define SM_AL   73728                   // A lo plane: 8 KB
#define SM_BIAS 81920                   // 256 floats = 1 KB
#define SM_TOT  82944

// split a float4 into hi/lo bf16 pairs (packed uint32: low half = first elem)
__device__ __forceinline__ void split4(float4 v, uint32_t& hi01, uint32_t& hi23,
                                       uint32_t& lo01, uint32_t& lo23) {
    __nv_bfloat162 h01 = __floats2bfloat162_rn(v.x, v.y);
    __nv_bfloat162 h23 = __floats2bfloat162_rn(v.z, v.w);
    __nv_bfloat162 l01 = __floats2bfloat162_rn(
        v.x - __bfloat162float(h01.x), v.y - __bfloat162float(h01.y));
    __nv_bfloat162 l23 = __floats2bfloat162_rn(
        v.z - __bfloat162float(h23.x), v.w - __bfloat162float(h23.y));
    hi01 = *(uint32_t*)&h01; hi23 = *(uint32_t*)&h23;
    lo01 = *(uint32_t*)&l01; lo23 = *(uint32_t*)&l23;
}

// ---------------------------------------------------------------------------
// HMMA input GEMM: P[r][g] = In[r]·W[g] + b1[g] + b2[g]
// Tile = 64 rows x 256 gates x K64. 512 threads = 16 warps (4 rowgrp x 4 colgrp).
// bf16 split-2: products hi*hi + hi*lo + lo*hi (lo*lo negligible), fp32 acc.
// ---------------------------------------------------------------------------
__global__ void __launch_bounds__(512, 1) input_gemm_mma(
    const float* __restrict__ In,   // [N, 64]
    const float* __restrict__ W,    // [256, 64]
    const float* __restrict__ b1,
    const float* __restrict__ b2,
    float* __restrict__ P,          // [N, 256]
    int N)
{
    extern __shared__ __align__(128) char sm[];
    float* sBias = (float*)(sm + SM_BIAS);

    const int tid  = threadIdx.x;
    const int wid  = tid >> 5;
    const int lane = tid & 31;
    const int gid  = lane >> 2;         // 0..7
    const int tig  = lane & 3;          // 0..3

    // ---- one-time W split into BH/BL planes (SW128 swizzled) + bias ----
    {
        int row  = tid >> 1;            // 0..255
        int half = tid & 1;             // elems [half*32, half*32+32)
        const float* wr = W + row * 64 + half * 32;
        uint32_t base = row * 128;
        uint32_t m    = ((uint32_t)(row & 7)) * 16;
        #pragma unroll
        for (int c = 0; c < 4; c++) {   // 4 chunks of 8 elems
            float4 v0 = *(const float4*)(wr + c * 8);
            float4 v1 = *(const float4*)(wr + c * 8 + 4);
            uint4 h, l;
            split4(v0, h.x, h.y, l.x, l.y);
            split4(v1, h.z, h.w, l.z, l.w);
            uint32_t off = base + (((uint32_t)(half * 64 + c * 16)) ^ m);
            *(uint4*)(sm + SM_BH + off) = h;
            *(uint4*)(sm + SM_BL + off) = l;
        }
        if (tid < 256) sBias[tid] = b1[tid] + b2[tid];
    }
    __syncthreads();

    const int rg = wid & 3, cg = wid >> 2;
    const int R0 = rg * 16, C0 = cg * 64;
    const uint32_t xm = ((uint32_t)gid) * 16;   // frag-load swizzle mask

    const int ntiles = N / 64;          // 5376
    const int stride = gridDim.x;
    int tile = blockIdx.x;
    if (tile >= ntiles) return;

    // A conversion identity
    const int arow = tid >> 3;          // 0..63
    const int aseg = tid & 7;           // 8 floats each
    const uint32_t am = ((uint32_t)(arow & 7)) * 16;

    float4 xr0 = *(const float4*)(In + ((size_t)tile * 64 + arow) * 64 + aseg * 8);
    float4 xr1 = *(const float4*)(In + ((size_t)tile * 64 + arow) * 64 + aseg * 8 + 4);

    for (; tile < ntiles; tile += stride) {
        // ---- split A tile into AH/AL planes ----
        {
            uint4 h, l;
            split4(xr0, h.x, h.y, l.x, l.y);
            split4(xr1, h.z, h.w, l.z, l.w);
            uint32_t off = arow * 128 + (((uint32_t)(aseg * 16)) ^ am);
            *(uint4*)(sm + SM_AH + off) = h;
            *(uint4*)(sm + SM_AL + off) = l;
        }
        __syncthreads();

        // prefetch next tile
        const int nxt = tile + stride;
        if (nxt < ntiles) {
            xr0 = *(const float4*)(In + ((size_t)nxt * 64 + arow) * 64 + aseg * 8);
            xr1 = *(const float4*)(In + ((size_t)nxt * 64 + arow) * 64 + aseg * 8 + 4);
        }

        // ---- MMA mainloop ----
        float acc[8][4];
        #pragma unroll
        for (int n = 0; n < 8; n++)
            { acc[n][0] = 0.f; acc[n][1] = 0.f; acc[n][2] = 0.f; acc[n][3] = 0.f; }

        #pragma unroll
        for (int kc = 0; kc < 4; kc++) {
            const uint32_t kb0 = (uint32_t)(kc * 32 + tig * 4);
            const uint32_t kb1 = kb0 + 16;
            const uint32_t ra  = (uint32_t)((R0 + gid) * 128);
            uint32_t ah0 = *(const uint32_t*)(sm + SM_AH + ra        + (kb0 ^ xm));
            uint32_t ah1 = *(const uint32_t*)(sm + SM_AH + ra + 1024 + (kb0 ^ xm));
            uint32_t ah2 = *(const uint32_t*)(sm + SM_AH + ra        + (kb1 ^ xm));
            uint32_t ah3 = *(const uint32_t*)(sm + SM_AH + ra + 1024 + (kb1 ^ xm));
            uint32_t al0 = *(const uint32_t*)(sm + SM_AL + ra        + (kb0 ^ xm));
            uint32_t al1 = *(const uint32_t*)(sm + SM_AL + ra + 1024 + (kb0 ^ xm));
            uint32_t al2 = *(const uint32_t*)(sm + SM_AL + ra        + (kb1 ^ xm));
            uint32_t al3 = *(const uint32_t*)(sm + SM_AL + ra + 1024 + (kb1 ^ xm));
            #pragma unroll
            for (int n8 = 0; n8 < 8; n8++) {
                const uint32_t rb = (uint32_t)((C0 + n8 * 8 + gid) * 128);
                uint32_t bh0 = *(const uint32_t*)(sm + SM_BH + rb + (kb0 ^ xm));
                uint32_t bh1 = *(const uint32_t*)(sm + SM_BH + rb + (kb1 ^ xm));
                uint32_t bl0 = *(const uint32_t*)(sm + SM_BL + rb + (kb0 ^ xm));
                uint32_t bl1 = *(const uint32_t*)(sm + SM_BL + rb + (kb1 ^ xm));
                mma_bf16(acc[n8], ah0, ah1, ah2, ah3, bh0, bh1);
                mma_bf16(acc[n8], ah0, ah1, ah2, ah3, bl0, bl1);
                mma_bf16(acc[n8], al0, al1, al2, al3, bh0, bh1);
            }
        }

        // ---- epilogue: add bias, stream to P ----
        {
            const size_t r0 = (size_t)tile * 64 + R0 + gid;
            #pragma unroll
            for (int n8 = 0; n8 < 8; n8++) {
                const int col = C0 + n8 * 8 + tig * 2;
                float2 bb = *(const float2*)&sBias[col];
                float2 v0 = make_float2(acc[n8][0] + bb.x, acc[n8][1] + bb.y);
                float2 v1 = make_float2(acc[n8][2] + bb.x, acc[n8][3] + bb.y);
                __stcs((float2*)(P + r0 * G + col), v0);
                __stcs((float2*)(P + (r0 + 8) * G + col), v1);
            }
        }
        __syncthreads();   // A planes safe to overwrite
    }
}

// ---------------------------------------------------------------------------
// Recurrent scan (R8/R10 — known good 425us): BT=4, 256 thr, 2 CTAs/SM.
// P includes bias.
// ---------------------------------------------------------------------------
template <bool WRITE_ALL>
__global__ void __launch_bounds__(256, 2) lstm_recur(
    const float* __restrict__ P,     // [BATCH, T, 256] (biases included)
    const float* __restrict__ Whh,   // [256, 64]
    float* __restrict__ hout)        // WRITE_ALL ? [BATCH,T,64] : [BATCH,64]
{
    __shared__ __align__(16) float sH[4 * 64];
    __shared__ __align__(16) float sGate[4 * G];

    const int tid = threadIdx.x;
    const int b0  = blockIdx.x * 4;
    const int g   = tid;
    const int gt  = g >> 6;              // warp-uniform

    ull w[32];
    {
        const ull* wp = (const ull*)(Whh + g * 64);
        #pragma unroll
        for (int i = 0; i < 32; i++) w[i] = wp[i];
    }

    const int eb = tid >> 6;             // 0..3
    const int ej = tid & 63;
    float c = 0.0f;

    sH[tid] = 0.0f;

    const float* pbase = P + ((size_t)b0 * T) * G + g;
    float pc[4];
    #pragma unroll
    for (int b = 0; b < 4; b++) pc[b] = pbase[(size_t)b * T * G];
    __syncthreads();

    for (int t = 0; t < T; t++) {
        float pn[4];
        if (t + 1 < T) {
            #pragma unroll
            for (int b = 0; b < 4; b++)
                pn[b] = __ldcs(&pbase[(size_t)b * T * G + (size_t)(t + 1) * G]);
        }

        ull acc[4];
        #pragma unroll
        for (int b = 0; b < 4; b++) acc[b] = 0ull;

        #pragma unroll
        for (int kg = 0; kg < 16; kg++) {
            ull w01 = w[2 * kg], w23 = w[2 * kg + 1];
            #pragma unroll
            for (int b = 0; b < 4; b++) {
                ulonglong2 hv = *(const ulonglong2*)&sH[b * 64 + kg * 4];
                FMA2(acc[b], w01, hv.x);
                FMA2(acc[b], w23, hv.y);
            }
        }

        #pragma unroll
        for (int b = 0; b < 4; b++) {
            float lo, hi;
            UNPACK2(lo, hi, acc[b]);
            float v = lo + hi + pc[b];
            sGate[b * G + g] = (gt == 2) ? fast_tanh(v) : fast_sigmoid(v);
        }
        __syncthreads();

        {
            float iv = sGate[eb * G + ej];
            float fv = sGate[eb * G + 64 + ej];
            float gv = sGate[eb * G + 128 + ej];
            float ov = sGate[eb * G + 192 + ej];
            c = fmaf(fv, c, iv * gv);
            float h = ov * fast_tanh(c);
            sH[tid] = h;
            if (WRITE_ALL) {
                __stcs(&hout[(size_t)(b0 + eb) * T * HD + (size_t)t * HD + ej], h);
            } else if (t == T - 1) {
                hout[(b0 + eb) * HD + ej] = h;
            }
        }
        __syncthreads();

        #pragma unroll
        for (int b = 0; b < 4; b++) pc[b] = pn[b];
    }
}

// ---------------------------------------------------------------------------
// Decoder v2 (R8/R10, unchanged): BT=4, 256 thr, 2 CTAs/SM.
// ---------------------------------------------------------------------------
__global__ void __launch_bounds__(256, 2) lstm_decoder(
    const float* __restrict__ Wih0, const float* __restrict__ bih0, const float* __restrict__ bhh0,
    const float* __restrict__ Wih1, const float* __restrict__ bih1, const float* __restrict__ bhh1,
    const float* __restrict__ Wfc,  const float* __restrict__ bfc,
    const float* __restrict__ h2last,
    float* __restrict__ out)   // [BATCH, PRED, 64]
{
    extern __shared__ __align__(16) char dyn[];
    ull*   sW1p  = (ull*)dyn;                      // [32][256] ull (64 KB)
    ull*   sWfcp = sW1p + 32 * 256;                // [32][64]  ull (16 KB)
    float* sB1   = (float*)(sWfcp + 32 * 64);      // [256]
    float* sBfc  = sB1 + 256;                      // [64]
    float* sIn   = sBfc + 64;                      // [4][64]
    float* sHm   = sIn + 4 * 64;                   // [4][64]
    float* sGate = sHm + 4 * 64;                   // [4][256]

    const int tid = threadIdx.x;
    const int b0  = blockIdx.x * 4;
    const int g   = tid;
    const int gt  = g >> 6;
    const int eb  = tid >> 6;            // 0..3
    const int ej  = tid & 63;

    ull wa[32];
    {
        const ull* w0 = (const ull*)(Wih0 + g * 64);
        #pragma unroll
        for (int i = 0; i < 32; i++) wa[i] = w0[i];
    }
    const float bias0 = bih0[g] + bhh0[g];
    const float ta = (gt == 2) ? 1.0f : 0.5f;
    const float s1 = (gt == 2) ? 1.0f : 0.5f;
    const float s2 = (gt == 2) ? 0.0f : 0.5f;

    {
        const ull* w1 = (const ull*)(Wih1 + tid * 64);
        #pragma unroll
        for (int i = 0; i < 32; i++) sW1p[i * 256 + tid] = w1[i];
        sB1[tid] = bih1[tid] + bhh1[tid];
        if (tid < 64) {
            const ull* wf = (const ull*)(Wfc + tid * 64);
            #pragma unroll
            for (int i = 0; i < 32; i++) sWfcp[i * 64 + tid] = wf[i];
            sBfc[tid] = bfc[tid];
        }
    }
    sIn[tid] = h2last[b0 * 64 + tid];
    __syncthreads();

    for (int s = 0; s < PRED; s++) {
        // ---- cell0 (weights in regs), src = sIn ----
        {
            ull acc[4];
            #pragma unroll
            for (int b = 0; b < 4; b++) acc[b] = 0ull;
            #pragma unroll
            for (int kg = 0; kg < 16; kg++) {
                ull w01 = wa[2 * kg], w23 = wa[2 * kg + 1];
                #pragma unroll
                for (int b = 0; b < 4; b++) {
                    ulonglong2 xv = *(const ulonglong2*)&sIn[b * 64 + kg * 4];
                    FMA2(acc[b], w01, xv.x);
                    FMA2(acc[b], w23, xv.y);
                }
            }
            #pragma unroll
            for (int b = 0; b < 4; b++) {
                float lo, hi;
                UNPACK2(lo, hi, acc[b]);
                float v = lo + hi + bias0;
                sGate[b * G + g] = fmaf(fast_tanh(v * ta), s1, s2);
            }
            __syncthreads();
            float iv = sGate[eb * G + ej];
            float gv = sGate[eb * G + 128 + ej];
            float ov = sGate[eb * G + 192 + ej];
            sHm[tid] = ov * fast_tanh(iv * gv);
            __syncthreads();
        }
        // ---- cell1 (weights from packed smem), src = sHm ----
        {
            ull acc[4];
            #pragma unroll
            for (int b = 0; b < 4; b++) acc[b] = 0ull;
            #pragma unroll
            for (int kg = 0; kg < 16; kg++) {
                ull w01 = sW1p[(2 * kg) * 256 + g];
                ull w23 = sW1p[(2 * kg + 1) * 256 + g];
                #pragma unroll
                for (int b = 0; b < 4; b++) {
                    ulonglong2 xv = *(const ulonglong2*)&sHm[b * 64 + kg * 4];
                    FMA2(acc[b], w01, xv.x);
                    FMA2(acc[b], w23, xv.y);
                }
            }
            float bias1 = sB1[g];
            #pragma unroll
            for (int b = 0; b < 4; b++) {
                float lo, hi;
                UNPACK2(lo, hi, acc[b]);
                float v = lo + hi + bias1;
                sGate[b * G + g] = fmaf(fast_tanh(v * ta), s1, s2);
            }
            __syncthreads();
            float iv = sGate[eb * G + ej];
            float gv = sGate[eb * G + 128 + ej];
            float ov = sGate[eb * G + 192 + ej];
            sHm[tid] = ov * fast_tanh(iv * gv);
            __syncthreads();
        }
        // ---- FC: one output per thread (eb, ej) ----
        {
            ull acc = 0ull;
            #pragma unroll
            for (int i = 0; i < 16; i++) {
                ull w01 = sWfcp[(2 * i) * 64 + ej];
                ull w23 = sWfcp[(2 * i + 1) * 64 + ej];
                ulonglong2 xv = *(const ulonglong2*)&sHm[eb * 64 + i * 4];
                FMA2(acc, w01, xv.x);
                FMA2(acc, w23, xv.y);
            }
            float lo, hi;
            UNPACK2(lo, hi, acc);
            float pred = lo + hi + sBfc[ej];
            out[(size_t)(b0 + eb) * PRED * HD + (size_t)s * HD + ej] = pred;
            sIn[tid] = pred;
            __syncthreads();
        }
    }
}

// ---------------------------------------------------------------------------
extern "C" void kernel_launch(void* const* d_in, const int* in_sizes, int n_in,
                              void* d_out, int out_size)
{
    const float* x    = (const float*)d_in[0];
    const float* Wih0 = (const float*)d_in[1];
    const float* Whh0 = (const float*)d_in[2];
    const float* bih0 = (const float*)d_in[3];
    const float* bhh0 = (const float*)d_in[4];
    const float* Wih1 = (const float*)d_in[5];
    const float* Whh1 = (const float*)d_in[6];
    const float* bih1 = (const float*)d_in[7];
    const float* bhh1 = (const float*)d_in[8];
    const float* Wfc  = (const float*)d_in[9];
    const float* bfc  = (const float*)d_in[10];
    float* out = (float*)d_out;

    float *pbuf = nullptr, *h1 = nullptr, *h2l = nullptr;
    cudaGetSymbolAddress((void**)&pbuf, g_p);
    cudaGetSymbolAddress((void**)&h1,   g_h1);
    cudaGetSymbolAddress((void**)&h2l,  g_h2last);

    const size_t smDec = (32 * 256 + 32 * 64) * sizeof(ull)
                       + (256 + 64 + 4 * 64 * 2 + 4 * G) * sizeof(float);
    cudaFuncSetAttribute(lstm_decoder, cudaFuncAttributeMaxDynamicSharedMemorySize, (int)smDec);
    cudaFuncSetAttribute(input_gemm_mma, cudaFuncAttributeMaxDynamicSharedMemorySize, SM_TOT);

    input_gemm_mma<<<148, 512, SM_TOT>>>(x, Wih0, bih0, bhh0, pbuf, NROWS);
    lstm_recur<true ><<<256, 256>>>(pbuf, Whh0, h1);

    input_gemm_mma<<<148, 512, SM_TOT>>>(h1, Wih1, bih1, bhh1, pbuf, NROWS);
    lstm_recur<false><<<256, 256>>>(pbuf, Whh1, h2l);

    lstm_decoder<<<256, 256, smDec>>>(Wih0, bih0, bhh0, Wih1, bih1, bhh1,
                                      Wfc, bfc, h2l, out);
}